// round 5
// baseline (speedup 1.0000x reference)
#include <cuda_runtime.h>

#define NN 8192
#define DIN 512
#define DOUT 64
#define HEADS 8
#define MWORDS 256
#define L2E 1.44269504088896f

__device__ float    g_Wh[NN * 512];         // [j][h*64+d], tf32-rounded
__device__ float    g_WhT[HEADS * 64 * NN]; // [h][d][j-permuted]
__device__ float    g_f1[HEADS * NN];       // * log2e
__device__ float    g_f2[HEADS * NN];       // * log2e
__device__ float    g_f2P[HEADS * NN];      // * log2e, j-permuted per 8
__device__ float    g_f2max[HEADS];
__device__ unsigned g_mask[NN * MWORDS];

// ---------------- helpers ----------------
__device__ __forceinline__ unsigned long long fma2(unsigned long long a,
                                                   unsigned long long b,
                                                   unsigned long long c) {
    unsigned long long d;
    asm("fma.rn.f32x2 %0, %1, %2, %3;" : "=l"(d) : "l"(a), "l"(b), "l"(c));
    return d;
}
__device__ __forceinline__ unsigned long long pack2(float x) {
    unsigned long long d;
    asm("mov.b64 %0, {%1, %1};" : "=l"(d) : "f"(x));
    return d;
}
__device__ __forceinline__ float2 unpack2(unsigned long long v) {
    float2 f;
    asm("mov.b64 {%0, %1}, %2;" : "=f"(f.x), "=f"(f.y) : "l"(v));
    return f;
}
__device__ __forceinline__ unsigned tf32r(float x) {
    unsigned r;
    asm("cvt.rna.tf32.f32 %0, %1;" : "=r"(r) : "f"(x));
    return r;
}
__device__ __forceinline__ float ex2f(float x) {
    float r;
    asm("ex2.approx.f32 %0, %1;" : "=f"(r) : "f"(x));
    return r;
}
__device__ __forceinline__ void mma_tf32(float c[4], unsigned a0, unsigned a1,
                                         unsigned a2, unsigned a3,
                                         unsigned b0, unsigned b1) {
    asm volatile(
        "mma.sync.aligned.m16n8k8.row.col.f32.tf32.tf32.f32 "
        "{%0,%1,%2,%3}, {%4,%5,%6,%7}, {%8,%9}, {%0,%1,%2,%3};"
        : "+f"(c[0]), "+f"(c[1]), "+f"(c[2]), "+f"(c[3])
        : "r"(a0), "r"(a1), "r"(a2), "r"(a3), "r"(b0), "r"(b1));
}
__device__ __forceinline__ void cp16(void* dst, const void* src) {
    unsigned d = (unsigned)__cvta_generic_to_shared(dst);
    asm volatile("cp.async.cg.shared.global [%0], [%1], 16;" :: "r"(d), "l"(src));
}
__device__ __forceinline__ void cp8(void* dst, const void* src) {
    unsigned d = (unsigned)__cvta_generic_to_shared(dst);
    asm volatile("cp.async.ca.shared.global [%0], [%1], 8;" :: "r"(d), "l"(src));
}
__device__ __forceinline__ void cp_commit() { asm volatile("cp.async.commit_group;"); }
__device__ __forceinline__ void cp_wait1()  { asm volatile("cp.async.wait_group 1;"); }

// ---------------- kernel 1: adj -> bitmask ----------------
__global__ __launch_bounds__(256) void mask_kernel(const int* __restrict__ adj) {
    const int UN = 8;
    long long w0 = ((long long)blockIdx.x * 8 + (threadIdx.x >> 5)) * UN;
    int lane = threadIdx.x & 31;
    int v[UN];
#pragma unroll
    for (int u = 0; u < UN; ++u) v[u] = adj[(w0 + u) * 32 + lane];
#pragma unroll
    for (int u = 0; u < UN; ++u) {
        unsigned b = __ballot_sync(0xffffffffu, v[u] > 0);
        if (lane == 0) g_mask[w0 + u] = b;
    }
}

// ---------------- kernel 2: Wh = x @ W (+ f1/f2, tf32-round) ----------------
__global__ __launch_bounds__(256, 2) void gemm_wh_kernel(
    const float* __restrict__ x, const float* __restrict__ W,
    const float* __restrict__ a1, const float* __restrict__ a2)
{
    __shared__ float As[16 * 128];
    __shared__ float Bs[16 * 64];
    const int h = blockIdx.y, row0 = blockIdx.x * 128, t = threadIdx.x;
    const int dg = t & 7, rg = t >> 3;
    const float* Wb = W + h * (DIN * DOUT);

    unsigned long long acc[4][4];
#pragma unroll
    for (int r = 0; r < 4; ++r)
#pragma unroll
        for (int q = 0; q < 4; ++q) acc[r][q] = 0ull;

    for (int kt = 0; kt < 32; ++kt) {
        __syncthreads();
#pragma unroll
        for (int s2 = 0; s2 < 2; ++s2) {
            int idx = t + s2 * 256;
            int row = idx >> 2, kq = idx & 3;
            float4 v = ((const float4*)x)[(long long)(row0 + row) * 128 + kt * 4 + kq];
            As[(kq * 4 + 0) * 128 + row] = v.x;
            As[(kq * 4 + 1) * 128 + row] = v.y;
            As[(kq * 4 + 2) * 128 + row] = v.z;
            As[(kq * 4 + 3) * 128 + row] = v.w;
        }
        {
            int k = t >> 4, dq = t & 15;
            ((float4*)Bs)[k * 16 + dq] = ((const float4*)Wb)[(kt * 16 + k) * 16 + dq];
        }
        __syncthreads();
#pragma unroll
        for (int k = 0; k < 16; ++k) {
            float4 av = *(const float4*)&As[k * 128 + rg * 4];
            const unsigned long long* bp = (const unsigned long long*)&Bs[k * 64 + dg * 8];
            unsigned long long b0 = bp[0], b1 = bp[1], b2 = bp[2], b3 = bp[3];
            unsigned long long p;
            p = pack2(av.x);
            acc[0][0] = fma2(p, b0, acc[0][0]); acc[0][1] = fma2(p, b1, acc[0][1]);
            acc[0][2] = fma2(p, b2, acc[0][2]); acc[0][3] = fma2(p, b3, acc[0][3]);
            p = pack2(av.y);
            acc[1][0] = fma2(p, b0, acc[1][0]); acc[1][1] = fma2(p, b1, acc[1][1]);
            acc[1][2] = fma2(p, b2, acc[1][2]); acc[1][3] = fma2(p, b3, acc[1][3]);
            p = pack2(av.z);
            acc[2][0] = fma2(p, b0, acc[2][0]); acc[2][1] = fma2(p, b1, acc[2][1]);
            acc[2][2] = fma2(p, b2, acc[2][2]); acc[2][3] = fma2(p, b3, acc[2][3]);
            p = pack2(av.w);
            acc[3][0] = fma2(p, b0, acc[3][0]); acc[3][1] = fma2(p, b1, acc[3][1]);
            acc[3][2] = fma2(p, b2, acc[3][2]); acc[3][3] = fma2(p, b3, acc[3][3]);
        }
    }

    float a1r[8], a2r[8];
#pragma unroll
    for (int q = 0; q < 8; ++q) {
        a1r[q] = a1[h * 64 + dg * 8 + q];
        a2r[q] = a2[h * 64 + dg * 8 + q];
    }
#pragma unroll
    for (int r = 0; r < 4; ++r) {
        int gi = row0 + rg * 4 + r;
        float vals[8];
#pragma unroll
        for (int q = 0; q < 4; ++q) {
            float2 f = unpack2(acc[r][q]);
            vals[2 * q]     = __uint_as_float(tf32r(f.x));
            vals[2 * q + 1] = __uint_as_float(tf32r(f.y));
        }
        float4 o0 = make_float4(vals[0], vals[1], vals[2], vals[3]);
        float4 o1 = make_float4(vals[4], vals[5], vals[6], vals[7]);
        ((float4*)g_Wh)[(long long)gi * 128 + h * 16 + dg * 2]     = o0;
        ((float4*)g_Wh)[(long long)gi * 128 + h * 16 + dg * 2 + 1] = o1;
        float s1 = 0.f, s2v = 0.f;
#pragma unroll
        for (int q = 0; q < 8; ++q) { s1 += vals[q] * a1r[q]; s2v += vals[q] * a2r[q]; }
#pragma unroll
        for (int d = 4; d; d >>= 1) {
            s1  += __shfl_down_sync(0xffffffffu, s1,  d, 8);
            s2v += __shfl_down_sync(0xffffffffu, s2v, d, 8);
        }
        if (dg == 0) {
            g_f1[h * NN + gi] = s1 * L2E;
            g_f2[h * NN + gi] = s2v * L2E;
        }
    }
}

// ---------------- kernel 2b: per-head max of f2 ----------------
__global__ __launch_bounds__(256) void f2max_kernel() {
    __shared__ float red[8];
    int h = blockIdx.x;
    float m = -3.4e38f;
    for (int i = threadIdx.x; i < NN; i += 256)
        m = fmaxf(m, g_f2[h * NN + i]);
#pragma unroll
    for (int s = 16; s; s >>= 1)
        m = fmaxf(m, __shfl_xor_sync(0xffffffffu, m, s));
    if ((threadIdx.x & 31) == 0) red[threadIdx.x >> 5] = m;
    __syncthreads();
    if (threadIdx.x < 8) {
        m = red[threadIdx.x];
#pragma unroll
        for (int s = 4; s; s >>= 1)
            m = fmaxf(m, __shfl_xor_sync(0x000000ffu, m, s));
        if (threadIdx.x == 0) g_f2max[h] = m;
    }
}

// ---------------- kernel 2c: transpose Wh -> [h][d][j'], permute f2 --------
// within-8 perm p(j): (a2 a1 a0) -> (a1 a0 a2); inverse: (b2 b1 b0) -> (b0 b2 b1)
__global__ __launch_bounds__(256) void transpose_kernel() {
    __shared__ float sh[64 * 72];
    const int jt = blockIdx.x, h = blockIdx.y, t = threadIdx.x;
    const long long j0 = (long long)jt * 64;
#pragma unroll
    for (int s = 0; s < 4; ++s) {
        int idx = t + s * 256;
        int j = idx >> 4, q = idx & 15;
        float4 v = ((const float4*)g_Wh)[(j0 + j) * 128 + h * 16 + q];
        sh[(q * 4 + 0) * 72 + j] = v.x;
        sh[(q * 4 + 1) * 72 + j] = v.y;
        sh[(q * 4 + 2) * 72 + j] = v.z;
        sh[(q * 4 + 3) * 72 + j] = v.w;
    }
    if (t < 64) {
        int jp = (t & ~7) | ((t & 3) << 1) | ((t >> 2) & 1);
        g_f2P[h * NN + j0 + jp] = g_f2[h * NN + j0 + t];
    }
    __syncthreads();
#pragma unroll
    for (int s = 0; s < 4; ++s) {
        int idx = t + s * 256;
        int d = idx >> 4, c = idx & 15;
        int jj = c * 4;
        float4 v;
        v.x = sh[d * 72 + ((jj & ~7) | (((jj + 0) & 1) << 2) | (((jj + 0) & 7) >> 1))];
        v.y = sh[d * 72 + ((jj & ~7) | (((jj + 1) & 1) << 2) | (((jj + 1) & 7) >> 1))];
        v.z = sh[d * 72 + ((jj & ~7) | (((jj + 2) & 1) << 2) | (((jj + 2) & 7) >> 1))];
        v.w = sh[d * 72 + ((jj & ~7) | (((jj + 3) & 1) << 2) | (((jj + 3) & 7) >> 1))];
        ((float4*)g_WhT)[(((long long)(h * 64 + d)) * NN + j0) / 4 + c] = v;
    }
}

// ---------------- kernel 3: attention (tf32 mma, cp.async dbl-buffer) ------
__global__ __launch_bounds__(256, 2) void attn_kernel(float* __restrict__ out) {
    __shared__ __align__(16) float    WhS[2][64 * 72];
    __shared__ __align__(16) float2   f2s[2][32];
    __shared__ __align__(16) unsigned maskS[2][256];

    const int h = blockIdx.y, row0 = blockIdx.x * 128, t = threadIdx.x;
    const int lane = t & 31, warp = t >> 5, gid = lane >> 2, tig = lane & 3;
    const int r0 = warp * 16 + gid, r1 = r0 + 8;
    const long long gr0 = row0 + r0, gr1 = row0 + r1;

    const float f2m = g_f2max[h];
    const float f1a = g_f1[h * NN + gr0], f1b = g_f1[h * NN + gr1];
    const float ea = f1a + f2m, eb = f1b + f2m;
    const float m0 = fmaxf(ea, 0.2f * ea), m1 = fmaxf(eb, 0.2f * eb);
    const float f1m0 = f1a - m0, c10 = fmaf(0.2f, f1a, -m0);
    const float f1m1 = f1b - m1, c11 = fmaf(0.2f, f1b, -m1);
    float l0 = 0.f, l1 = 0.f;

    float acc[8][4];
#pragma unroll
    for (int nc = 0; nc < 8; ++nc)
#pragma unroll
        for (int q = 0; q < 4; ++q) acc[nc][q] = 0.f;

    // staging map: thread t -> row sd (0..63), chunk group sc (0..3),
    // copies 16B chunks c = sc*4+s (c in 0..15, 4 floats each) of that row.
    const int sd = t >> 2, sc = t & 3;
#define STAGE(jt, b) do {                                                     \
        long long js = (long long)(jt) * 64;                                  \
        const float* srow = &g_WhT[((long long)(h * 64 + sd)) * NN + js];     \
        _Pragma("unroll")                                                     \
        for (int s = 0; s < 4; ++s) {                                         \
            int c = sc * 4 + s;                                               \
            cp16(&WhS[b][sd * 72 + c * 4], srow + c * 4);                     \
        }                                                                     \
        if (t < 128) cp8(&maskS[b][t * 2],                                    \
                         &g_mask[(long long)(row0 + t) * MWORDS + (jt) * 2]); \
        if (t < 16)  cp16(&f2s[b][t * 2], &g_f2P[h * NN + js + t * 4]);       \
    } while (0)

    STAGE(0, 0);
    cp_commit();

    for (int jt = 0; jt < 128; ++jt) {
        const int cur = jt & 1;
        if (jt + 1 < 128) STAGE(jt + 1, cur ^ 1);
        cp_commit();
        cp_wait1();
        __syncthreads();

        const unsigned mr0a = maskS[cur][r0 * 2], mr0b = maskS[cur][r0 * 2 + 1];
        const unsigned mr1a = maskS[cur][r1 * 2], mr1b = maskS[cur][r1 * 2 + 1];
        const float* whb = &WhS[cur][gid * 72 + tig * 2];

#pragma unroll
        for (int kc = 0; kc < 8; ++kc) {
            const float2 f2p = f2s[cur][kc * 4 + tig];
            float s0 = fmaxf(f1m0 + f2p.x, fmaf(0.2f, f2p.x, c10));
            float s1 = fmaxf(f1m1 + f2p.x, fmaf(0.2f, f2p.x, c11));
            float s2 = fmaxf(f1m0 + f2p.y, fmaf(0.2f, f2p.y, c10));
            float s3 = fmaxf(f1m1 + f2p.y, fmaf(0.2f, f2p.y, c11));
            const int k0 = kc * 8 + tig, b0 = k0 & 31, b1 = (k0 + 4) & 31;
            const unsigned w0 = (kc < 4) ? mr0a : mr0b;
            const unsigned w1 = (kc < 4) ? mr1a : mr1b;
            if (!((w0 >> b0) & 1u)) s0 = -3.0e38f;
            if (!((w1 >> b0) & 1u)) s1 = -3.0e38f;
            if (!((w0 >> b1) & 1u)) s2 = -3.0e38f;
            if (!((w1 >> b1) & 1u)) s3 = -3.0e38f;
            const unsigned a0 = tf32r(ex2f(s0)), a1 = tf32r(ex2f(s1));
            const unsigned a2 = tf32r(ex2f(s2)), a3 = tf32r(ex2f(s3));
            l0 += __uint_as_float(a0) + __uint_as_float(a2);
            l1 += __uint_as_float(a1) + __uint_as_float(a3);
#pragma unroll
            for (int nc = 0; nc < 8; ++nc) {
                const float2 bb = *(const float2*)(whb + nc * 576 + kc * 8);
                mma_tf32(acc[nc], a0, a1, a2, a3,
                         __float_as_uint(bb.x), __float_as_uint(bb.y));
            }
        }
        __syncthreads();
    }

    l0 += __shfl_xor_sync(0xffffffffu, l0, 1);
    l0 += __shfl_xor_sync(0xffffffffu, l0, 2);
    l1 += __shfl_xor_sync(0xffffffffu, l1, 1);
    l1 += __shfl_xor_sync(0xffffffffu, l1, 2);
    const float inv0 = 1.0f / l0, inv1 = 1.0f / l1;

#pragma unroll
    for (int nc = 0; nc < 8; ++nc) {
        const int col = h * 64 + nc * 8 + tig * 2;
        ((float2*)out)[(gr0 * 512 + col) >> 1] =
            make_float2(acc[nc][0] * inv0, acc[nc][1] * inv0);
        ((float2*)out)[(gr1 * 512 + col) >> 1] =
            make_float2(acc[nc][2] * inv1, acc[nc][3] * inv1);
    }
}

// ---------------- launch ----------------
extern "C" void kernel_launch(void* const* d_in, const int* in_sizes, int n_in,
                              void* d_out, int out_size) {
    const float* x   = (const float*)d_in[0];
    const int*   adj = (const int*)d_in[1];
    const float* W   = (const float*)d_in[2];
    const float* a1  = (const float*)d_in[3];
    const float* a2  = (const float*)d_in[4];
    float* out = (float*)d_out;

    mask_kernel<<<(NN * MWORDS) / 64, 256>>>(adj);
    gemm_wh_kernel<<<dim3(NN / 128, HEADS), 256>>>(x, W, a1, a2);
    f2max_kernel<<<HEADS, 256>>>();
    transpose_kernel<<<dim3(NN / 64, HEADS), 256>>>();
    attn_kernel<<<dim3(NN / 128, HEADS), 256>>>(out);
}